// round 15
// baseline (speedup 1.0000x reference)
#include <cuda_runtime.h>
#include <math.h>
#include <float.h>

#define D_MODEL 1024
#define NUM_HEADS 16
#define D_K 64
#define SEQ 2048
#define BATCH 4
#define NX (BATCH * SEQ * D_MODEL)
#define NW (D_MODEL * D_MODEL)

// Scratch (static device globals -- no runtime allocation allowed)
__device__ float g_q[NX];
__device__ float g_k[NX];
__device__ float g_v[NX];
__device__ float g_attn[NX];
__device__ float g_xt[NX];
__device__ float g_wqt[NW];
__device__ float g_wkt[NW];
__device__ float g_wvt[NW];
__device__ float g_wot[NW];
__device__ float g_bqt[D_MODEL];

// ---------------------------------------------------------------------------
// tf32 helpers
// ---------------------------------------------------------------------------
__device__ __forceinline__ unsigned f2tf(float x) {
    unsigned u;
    asm("cvt.rna.tf32.f32 %0, %1;" : "=r"(u) : "f"(x));
    return u;
}

__device__ __forceinline__ void mma_tf32(float c[4], const unsigned a[4],
                                         unsigned b0, unsigned b1) {
    asm volatile(
        "mma.sync.aligned.m16n8k8.row.col.f32.tf32.tf32.f32 "
        "{%0,%1,%2,%3}, {%4,%5,%6,%7}, {%8,%9}, {%0,%1,%2,%3};\n"
        : "+f"(c[0]), "+f"(c[1]), "+f"(c[2]), "+f"(c[3])
        : "r"(a[0]), "r"(a[1]), "r"(a[2]), "r"(a[3]), "r"(b0), "r"(b1));
}

__device__ __forceinline__ void cpa16(unsigned s, const void* g) {
    asm volatile("cp.async.cg.shared.global [%0], [%1], 16;" :: "r"(s), "l"(g));
}

// ---------------------------------------------------------------------------
// Prep: pre-round x and weights to tf32-in-f32; fold 0.125 softmax scale
// into wq and bq. One elementwise pass, float4 per thread.
// Ranges: [0,NX) xt | [NX,+NW) wqt(*0.125) | +NW wkt | +NW wvt | +NW wot |
//         [+1024) bqt(*0.125, no rounding -- bias adds stay f32)
// ---------------------------------------------------------------------------
__global__ __launch_bounds__(256) void prep_tf32(
    const float* __restrict__ x,  const float* __restrict__ wq,
    const float* __restrict__ bq, const float* __restrict__ wk,
    const float* __restrict__ wv, const float* __restrict__ wo,
    float* __restrict__ xt,  float* __restrict__ wqt,
    float* __restrict__ bqt, float* __restrict__ wkt,
    float* __restrict__ wvt, float* __restrict__ wot)
{
    long i = ((long)blockIdx.x * 256 + threadIdx.x) * 4;
    if (i < NX) {
        float4 v = *(const float4*)&x[i];
        *(uint4*)&xt[i] = make_uint4(f2tf(v.x), f2tf(v.y), f2tf(v.z), f2tf(v.w));
    } else if (i < NX + (long)NW) {
        long j = i - NX;
        float4 v = *(const float4*)&wq[j];
        *(uint4*)&wqt[j] = make_uint4(f2tf(v.x * 0.125f), f2tf(v.y * 0.125f),
                                      f2tf(v.z * 0.125f), f2tf(v.w * 0.125f));
    } else if (i < NX + 2L * NW) {
        long j = i - NX - NW;
        float4 v = *(const float4*)&wk[j];
        *(uint4*)&wkt[j] = make_uint4(f2tf(v.x), f2tf(v.y), f2tf(v.z), f2tf(v.w));
    } else if (i < NX + 3L * NW) {
        long j = i - NX - 2L * NW;
        float4 v = *(const float4*)&wv[j];
        *(uint4*)&wvt[j] = make_uint4(f2tf(v.x), f2tf(v.y), f2tf(v.z), f2tf(v.w));
    } else if (i < NX + 4L * NW) {
        long j = i - NX - 3L * NW;
        float4 v = *(const float4*)&wo[j];
        *(uint4*)&wot[j] = make_uint4(f2tf(v.x), f2tf(v.y), f2tf(v.z), f2tf(v.w));
    } else if (i < NX + 4L * NW + D_MODEL) {
        long j = i - NX - 4L * NW;
        float4 v = *(const float4*)&bq[j];
        *(float4*)&bqt[j] = make_float4(v.x * 0.125f, v.y * 0.125f,
                                        v.z * 0.125f, v.w * 0.125f);
    }
}

// ---------------------------------------------------------------------------
// TF32 tensor-core GEMM, cp.async 2-stage pipeline, ZERO cvt (operands are
// pre-rounded tf32-in-f32). C[M,N] = A[M,K] @ Bz[K,N] + biasz[N].
// BM=128, BN=128, BK=32. 256 threads = 8 warps (2m x 4n), warp tile 64x32.
// As: m-major [128][36]; Bs: k-major [32][136]; conflict-free frag loads.
// __launch_bounds__(256,2) pins regs <=128 so 2 blocks/SM co-reside.
// round_out=1: outputs written tf32-rounded (consumed by flash/out-proj).
// ---------------------------------------------------------------------------
#define GA_STR 36
#define GB_STR 136
#define G_ABUF (128 * GA_STR)
#define G_BBUF (32 * GB_STR)
#define G_SMEM ((2 * (G_ABUF + G_BBUF)) * 4)

__global__ __launch_bounds__(256, 2) void gemm_tc(
    const float* __restrict__ A,
    const float* __restrict__ B0, const float* __restrict__ B1,
    const float* __restrict__ B2,
    const float* __restrict__ bias0, const float* __restrict__ bias1,
    const float* __restrict__ bias2,
    float* __restrict__ C0, float* __restrict__ C1, float* __restrict__ C2,
    int M, int N, int K, int round_out)
{
    extern __shared__ unsigned gsm[];
    unsigned* As = gsm;                    // 2 x 128x36
    unsigned* Bs = gsm + 2 * G_ABUF;       // 2 x 32x136

    int z = blockIdx.z;
    const float* B    = (z == 0) ? B0    : (z == 1) ? B1    : B2;
    const float* bias = (z == 0) ? bias0 : (z == 1) ? bias1 : bias2;
    float*       C    = (z == 0) ? C0    : (z == 1) ? C1    : C2;

    int t    = threadIdx.x;
    int lane = t & 31;
    int w    = t >> 5;
    int wm   = w >> 2;         // 0..1
    int wn   = w & 3;          // 0..3
    int bm   = blockIdx.y * 128;
    int bn   = blockIdx.x * 128;
    int lq   = lane >> 2;      // 0..7
    int lr4  = lane & 3;       // 0..3

    // loader indices: 16 floats per thread for each of A and B
    int am = t >> 1;           // 0..127
    int ak = (t & 1) * 16;     // 0 or 16
    int br = t >> 3;           // 0..31
    int bc = (t & 7) * 16;     // 0..112

    unsigned as_base = (unsigned)__cvta_generic_to_shared(As);
    unsigned bs_base = (unsigned)__cvta_generic_to_shared(Bs);

    float acc[4][4][4];
    #pragma unroll
    for (int mt = 0; mt < 4; mt++)
        #pragma unroll
        for (int nt = 0; nt < 4; nt++)
            #pragma unroll
            for (int i = 0; i < 4; i++) acc[mt][nt][i] = 0.f;

    const int KI = K >> 5;

    // prologue: stage 0
    {
        const float* Ag = &A[(size_t)(bm + am) * K + ak];
        unsigned ad = as_base + (am * GA_STR + ak) * 4;
        cpa16(ad,      Ag);
        cpa16(ad + 16, Ag + 4);
        cpa16(ad + 32, Ag + 8);
        cpa16(ad + 48, Ag + 12);
        const float* Bg = &B[(size_t)br * N + bn + bc];
        unsigned bd = bs_base + (br * GB_STR + bc) * 4;
        cpa16(bd,      Bg);
        cpa16(bd + 16, Bg + 4);
        cpa16(bd + 32, Bg + 8);
        cpa16(bd + 48, Bg + 12);
        asm volatile("cp.async.commit_group;");
    }

    for (int it = 0; it < KI; it++) {
        int cur = it & 1;
        if (it + 1 < KI) {
            int kb = (it + 1) << 5;
            int nxt = (it + 1) & 1;
            const float* Ag = &A[(size_t)(bm + am) * K + kb + ak];
            unsigned ad = as_base + (nxt * G_ABUF + am * GA_STR + ak) * 4;
            cpa16(ad,      Ag);
            cpa16(ad + 16, Ag + 4);
            cpa16(ad + 32, Ag + 8);
            cpa16(ad + 48, Ag + 12);
            const float* Bg = &B[(size_t)(kb + br) * N + bn + bc];
            unsigned bd = bs_base + (nxt * G_BBUF + br * GB_STR + bc) * 4;
            cpa16(bd,      Bg);
            cpa16(bd + 16, Bg + 4);
            cpa16(bd + 32, Bg + 8);
            cpa16(bd + 48, Bg + 12);
            asm volatile("cp.async.commit_group;");
            asm volatile("cp.async.wait_group 1;");
        } else {
            asm volatile("cp.async.wait_group 0;");
        }
        __syncthreads();

        const unsigned* Ac = As + cur * G_ABUF;
        const unsigned* Bc = Bs + cur * G_BBUF;

        #pragma unroll
        for (int k8 = 0; k8 < 4; k8++) {
            int kc = k8 * 8 + lr4;
            unsigned a[4][4];
            #pragma unroll
            for (int mt = 0; mt < 4; mt++) {
                int mr = wm * 64 + mt * 16 + lq;
                a[mt][0] = Ac[mr * GA_STR + kc];
                a[mt][1] = Ac[(mr + 8) * GA_STR + kc];
                a[mt][2] = Ac[mr * GA_STR + kc + 4];
                a[mt][3] = Ac[(mr + 8) * GA_STR + kc + 4];
            }
            unsigned b[4][2];
            #pragma unroll
            for (int nt = 0; nt < 4; nt++) {
                int nc = wn * 32 + nt * 8 + lq;
                b[nt][0] = Bc[kc * GB_STR + nc];
                b[nt][1] = Bc[(kc + 4) * GB_STR + nc];
            }
            #pragma unroll
            for (int mt = 0; mt < 4; mt++)
                #pragma unroll
                for (int nt = 0; nt < 4; nt++)
                    mma_tf32(acc[mt][nt], a[mt], b[nt][0], b[nt][1]);
        }
        __syncthreads();
    }

    // epilogue (round_out: emit tf32-rounded for downstream consumers)
    #pragma unroll
    for (int nt = 0; nt < 4; nt++) {
        int col = bn + wn * 32 + nt * 8 + 2 * lr4;
        float2 bi = *(const float2*)&bias[col];
        #pragma unroll
        for (int mt = 0; mt < 4; mt++) {
            int r0 = bm + wm * 64 + mt * 16 + lq;
            float2 o0 = make_float2(acc[mt][nt][0] + bi.x, acc[mt][nt][1] + bi.y);
            float2 o1 = make_float2(acc[mt][nt][2] + bi.x, acc[mt][nt][3] + bi.y);
            if (round_out) {
                o0.x = __uint_as_float(f2tf(o0.x));
                o0.y = __uint_as_float(f2tf(o0.y));
                o1.x = __uint_as_float(f2tf(o1.x));
                o1.y = __uint_as_float(f2tf(o1.y));
            }
            *(float2*)&C[(size_t)r0 * N + col] = o0;
            *(float2*)&C[(size_t)(r0 + 8) * N + col] = o1;
        }
    }
}

// ---------------------------------------------------------------------------
// TF32 tensor-core causal flash attention, 128q x 64k tiles (R13-proven).
// Inputs Q/K/V are pre-rounded tf32-in-f32 (Q pre-scaled) -> loaders are
// plain copies, no cvt. KEY PERMUTATION as R13 (P never touches smem).
// Smem (floats): Qs[128][68], Ks[64][72] (d-major), Vs[64][72].
// ---------------------------------------------------------------------------
#define FQ_STR 68
#define FK_STR 72
#define FA_SMEM ((128 * FQ_STR + 64 * FK_STR * 2) * 4)

__global__ __launch_bounds__(256, 2) void flash_attn_tc(
    const float* __restrict__ Q, const float* __restrict__ K,
    const float* __restrict__ V, float* __restrict__ O)
{
    extern __shared__ unsigned usm[];
    unsigned* Qs  = usm;                         // 128*68
    unsigned* Ks  = Qs + 128 * FQ_STR;           // 64*72   [d][key]
    unsigned* Vsm = Ks + 64 * FK_STR;            // 64*72   [key][d]

    int bh = blockIdx.x;                  // 0..63
    int qt = 15 - blockIdx.y;             // long blocks first
    int b  = bh >> 4;
    int h  = bh & 15;
    int qb = qt * 128;

    const float* Qbase = Q + (size_t)b * SEQ * D_MODEL + h * D_K;
    const float* Kbase = K + (size_t)b * SEQ * D_MODEL + h * D_K;
    const float* Vbase = V + (size_t)b * SEQ * D_MODEL + h * D_K;
    float*       Obase = O + (size_t)b * SEQ * D_MODEL + h * D_K;

    int t    = threadIdx.x;
    int lane = t & 31;
    int w    = t >> 5;
    int lq   = lane >> 2;      // 0..7
    int lr4  = lane & 3;       // 0..3
    int rw   = w * 16 + lq;
    int pl   = (lq & 1) ? (lq >> 1) + 4 : (lq >> 1);

    // ---- load Q tile (pre-scaled, pre-rounded: straight copy) ----
    {
        int lr  = t >> 4;
        int ld4 = (t & 15) * 4;
        #pragma unroll
        for (int c = 0; c < 8; c++) {
            int r = lr + c * 16;
            *(uint4*)&Qs[r * FQ_STR + ld4] =
                *(const uint4*)&Qbase[(size_t)(qb + r) * D_MODEL + ld4];
        }
    }

    float o[8][4];
    #pragma unroll
    for (int nt = 0; nt < 8; nt++)
        #pragma unroll
        for (int i = 0; i < 4; i++) o[nt][i] = 0.f;

    float m0 = -FLT_MAX, m1 = -FLT_MAX, l0 = 0.f, l1 = 0.f;

    int kr = t & 63;
    int kg = t >> 6;
    int lr = t >> 4;
    int ld4 = (t & 15) * 4;

    int nkt = 2 * qt + 2;
    for (int kt = 0; kt < nkt; kt++) {
        int kb = kt * 64;
        __syncthreads();

        // K transposed: Ks[d][key] (no cvt)
        #pragma unroll
        for (int i = 0; i < 4; i++) {
            int d = kg * 16 + i * 4;
            uint4 k4 = *(const uint4*)&Kbase[(size_t)(kb + kr) * D_MODEL + d];
            Ks[(d + 0) * FK_STR + kr] = k4.x;
            Ks[(d + 1) * FK_STR + kr] = k4.y;
            Ks[(d + 2) * FK_STR + kr] = k4.z;
            Ks[(d + 3) * FK_STR + kr] = k4.w;
        }
        // V natural: Vs[key][d] (no cvt)
        #pragma unroll
        for (int c = 0; c < 4; c++) {
            int r = lr + c * 16;
            *(uint4*)&Vsm[r * FK_STR + ld4] =
                *(const uint4*)&Vbase[(size_t)(kb + r) * D_MODEL + ld4];
        }
        __syncthreads();

        // ---- S = Q @ K^T with permuted B keys ----
        float s[8][4];
        #pragma unroll
        for (int nt = 0; nt < 8; nt++)
            #pragma unroll
            for (int i = 0; i < 4; i++) s[nt][i] = 0.f;

        #pragma unroll
        for (int k8 = 0; k8 < 8; k8++) {
            int kc = k8 * 8 + lr4;
            unsigned a[4];
            a[0] = Qs[rw * FQ_STR + kc];
            a[1] = Qs[(rw + 8) * FQ_STR + kc];
            a[2] = Qs[rw * FQ_STR + kc + 4];
            a[3] = Qs[(rw + 8) * FQ_STR + kc + 4];
            #pragma unroll
            for (int nt = 0; nt < 8; nt++) {
                unsigned b0 = Ks[kc * FK_STR + nt * 8 + pl];
                unsigned b1 = Ks[(kc + 4) * FK_STR + nt * 8 + pl];
                mma_tf32(s[nt], a, b0, b1);
            }
        }

        // ---- causal mask on permuted keys ----
        if (kt >= 2 * qt) {
            int row0 = qb + rw;
            #pragma unroll
            for (int nt = 0; nt < 8; nt++) {
                int key0 = kb + nt * 8 + lr4;
                int key1 = key0 + 4;
                if (key0 > row0)     s[nt][0] = -FLT_MAX;
                if (key1 > row0)     s[nt][1] = -FLT_MAX;
                if (key0 > row0 + 8) s[nt][2] = -FLT_MAX;
                if (key1 > row0 + 8) s[nt][3] = -FLT_MAX;
            }
        }

        // ---- online softmax, fully in registers ----
        {
            float a0 = -FLT_MAX, a1 = -FLT_MAX;
            #pragma unroll
            for (int nt = 0; nt < 8; nt++) {
                a0 = fmaxf(a0, fmaxf(s[nt][0], s[nt][1]));
                a1 = fmaxf(a1, fmaxf(s[nt][2], s[nt][3]));
            }
            a0 = fmaxf(a0, __shfl_xor_sync(0xffffffffu, a0, 1));
            a0 = fmaxf(a0, __shfl_xor_sync(0xffffffffu, a0, 2));
            a1 = fmaxf(a1, __shfl_xor_sync(0xffffffffu, a1, 1));
            a1 = fmaxf(a1, __shfl_xor_sync(0xffffffffu, a1, 2));
            float mn0 = fmaxf(m0, a0), mn1 = fmaxf(m1, a1);
            float c0 = __expf(m0 - mn0), c1 = __expf(m1 - mn1);
            float sum0 = 0.f, sum1 = 0.f;
            #pragma unroll
            for (int nt = 0; nt < 8; nt++) {
                float p0 = __expf(s[nt][0] - mn0);
                float p1 = __expf(s[nt][1] - mn0);
                float p2 = __expf(s[nt][2] - mn1);
                float p3 = __expf(s[nt][3] - mn1);
                sum0 += p0 + p1;
                sum1 += p2 + p3;
                s[nt][0] = __uint_as_float(f2tf(p0));
                s[nt][1] = __uint_as_float(f2tf(p1));
                s[nt][2] = __uint_as_float(f2tf(p2));
                s[nt][3] = __uint_as_float(f2tf(p3));
            }
            sum0 += __shfl_xor_sync(0xffffffffu, sum0, 1);
            sum0 += __shfl_xor_sync(0xffffffffu, sum0, 2);
            sum1 += __shfl_xor_sync(0xffffffffu, sum1, 1);
            sum1 += __shfl_xor_sync(0xffffffffu, sum1, 2);
            l0 = l0 * c0 + sum0;
            l1 = l1 * c1 + sum1;
            m0 = mn0; m1 = mn1;
            #pragma unroll
            for (int nt = 0; nt < 8; nt++) {
                o[nt][0] *= c0; o[nt][1] *= c0;
                o[nt][2] *= c1; o[nt][3] *= c1;
            }
        }

        // ---- O += P @ V : A-fragment directly from s registers ----
        #pragma unroll
        for (int k8 = 0; k8 < 8; k8++) {
            int kc = k8 * 8 + lr4;
            unsigned a[4];
            a[0] = __float_as_uint(s[k8][0]);
            a[1] = __float_as_uint(s[k8][2]);
            a[2] = __float_as_uint(s[k8][1]);
            a[3] = __float_as_uint(s[k8][3]);
            #pragma unroll
            for (int nt = 0; nt < 8; nt++) {
                unsigned b0 = Vsm[kc * FK_STR + nt * 8 + lq];
                unsigned b1 = Vsm[(kc + 4) * FK_STR + nt * 8 + lq];
                mma_tf32(o[nt], a, b0, b1);
            }
        }
    }

    // ---- normalize + write O tf32-rounded (consumed by out-proj) ----
    {
        float inv0 = 1.0f / l0;
        float inv1 = 1.0f / l1;
        int r0 = qb + rw;
        #pragma unroll
        for (int nt = 0; nt < 8; nt++) {
            int col = nt * 8 + 2 * lr4;
            float2 v0 = make_float2(__uint_as_float(f2tf(o[nt][0] * inv0)),
                                    __uint_as_float(f2tf(o[nt][1] * inv0)));
            float2 v1 = make_float2(__uint_as_float(f2tf(o[nt][2] * inv1)),
                                    __uint_as_float(f2tf(o[nt][3] * inv1)));
            *(float2*)&Obase[(size_t)r0 * D_MODEL + col] = v0;
            *(float2*)&Obase[(size_t)(r0 + 8) * D_MODEL + col] = v1;
        }
    }
}

// ---------------------------------------------------------------------------
// Host launcher
// ---------------------------------------------------------------------------
extern "C" void kernel_launch(void* const* d_in, const int* in_sizes, int n_in,
                              void* d_out, int out_size)
{
    const float* x  = (const float*)d_in[0];
    const float* wq = (const float*)d_in[1];
    const float* bq = (const float*)d_in[2];
    const float* wk = (const float*)d_in[3];
    const float* bk = (const float*)d_in[4];
    const float* wv = (const float*)d_in[5];
    const float* bv = (const float*)d_in[6];
    const float* wo = (const float*)d_in[7];
    const float* bo = (const float*)d_in[8];
    float* out = (float*)d_out;

    int M = in_sizes[0] / D_MODEL;   // B*S = 8192

    float *q, *k, *v, *attn, *xt, *wqt, *wkt, *wvt, *wot, *bqt;
    cudaGetSymbolAddress((void**)&q,    g_q);
    cudaGetSymbolAddress((void**)&k,    g_k);
    cudaGetSymbolAddress((void**)&v,    g_v);
    cudaGetSymbolAddress((void**)&attn, g_attn);
    cudaGetSymbolAddress((void**)&xt,   g_xt);
    cudaGetSymbolAddress((void**)&wqt,  g_wqt);
    cudaGetSymbolAddress((void**)&wkt,  g_wkt);
    cudaGetSymbolAddress((void**)&wvt,  g_wvt);
    cudaGetSymbolAddress((void**)&wot,  g_wot);
    cudaGetSymbolAddress((void**)&bqt,  g_bqt);

    cudaFuncSetAttribute(gemm_tc,
                         cudaFuncAttributeMaxDynamicSharedMemorySize, G_SMEM);
    cudaFuncSetAttribute(flash_attn_tc,
                         cudaFuncAttributeMaxDynamicSharedMemorySize, FA_SMEM);

    // prep: pre-round x + weights (fold 0.125 into wq/bq)
    long total = (long)NX + 4L * NW + D_MODEL;
    int pblocks = (int)((total / 4 + 255) / 256);
    prep_tf32<<<pblocks, 256>>>(x, wq, bq, wk, wv, wo,
                                xt, wqt, bqt, wkt, wvt, wot);

    dim3 gblk(256);

    // Fused QKV projections (tf32-rounded outputs)
    dim3 ggrd3(D_MODEL / 128, M / 128, 3);
    gemm_tc<<<ggrd3, gblk, G_SMEM>>>(xt, wqt, wkt, wvt, bqt, bk, bv,
                                     q, k, v, M, D_MODEL, D_MODEL, 1);

    dim3 fgrd(BATCH * NUM_HEADS, SEQ / 128);
    flash_attn_tc<<<fgrd, 256, FA_SMEM>>>(q, k, v, attn);

    // Output projection (full f32 output)
    dim3 ggrd1(D_MODEL / 128, M / 128, 1);
    gemm_tc<<<ggrd1, gblk, G_SMEM>>>(attn, wot, wot, wot, bo, bo, bo,
                                     out, out, out, M, D_MODEL, D_MODEL, 0);
}

// round 16
// speedup vs baseline: 1.1574x; 1.1574x over previous
#include <cuda_runtime.h>
#include <math.h>
#include <float.h>

#define D_MODEL 1024
#define NUM_HEADS 16
#define D_K 64
#define SEQ 2048
#define BATCH 4

// Scratch (static device globals -- no runtime allocation allowed)
__device__ float g_q[BATCH * SEQ * D_MODEL];
__device__ float g_k[BATCH * SEQ * D_MODEL];
__device__ float g_v[BATCH * SEQ * D_MODEL];
__device__ float g_attn[BATCH * SEQ * D_MODEL];

// ---------------------------------------------------------------------------
// tf32 helpers
// ---------------------------------------------------------------------------
__device__ __forceinline__ unsigned f2tf(float x) {
    unsigned u;
    asm("cvt.rna.tf32.f32 %0, %1;" : "=r"(u) : "f"(x));
    return u;
}

__device__ __forceinline__ void mma_tf32(float c[4], const unsigned a[4],
                                         unsigned b0, unsigned b1) {
    asm volatile(
        "mma.sync.aligned.m16n8k8.row.col.f32.tf32.tf32.f32 "
        "{%0,%1,%2,%3}, {%4,%5,%6,%7}, {%8,%9}, {%0,%1,%2,%3};\n"
        : "+f"(c[0]), "+f"(c[1]), "+f"(c[2]), "+f"(c[3])
        : "r"(a[0]), "r"(a[1]), "r"(a[2]), "r"(a[3]), "r"(b0), "r"(b1));
}

// ---------------------------------------------------------------------------
// TF32 tensor-core GEMM with fused bias. BM=64 / 3 blocks-per-SM variant:
// cross-block co-residency is the (empirically only) working latency hider,
// so we scale it: smaller tile -> 26.6KB smem + <=85 regs -> 3 blocks/SM.
// C[M,N] = A[M,K] @ Bz[K,N] + biasz[N], operand set selected by blockIdx.z.
// BM=64, BN=128, BK=32. 256 threads = 8 warps (2m x 4n), warp tile 32x32.
// As: m-major [64][36]; Bs: k-major [32][136]; conflict-free frag loads.
// cvt.rna at global->smem store time (1x per element, R13-proven).
// ---------------------------------------------------------------------------
#define GA_STR 36
#define GB_STR 136

__global__ __launch_bounds__(256, 3) void gemm_tc(
    const float* __restrict__ A,
    const float* __restrict__ B0, const float* __restrict__ B1,
    const float* __restrict__ B2,
    const float* __restrict__ bias0, const float* __restrict__ bias1,
    const float* __restrict__ bias2,
    float* __restrict__ C0, float* __restrict__ C1, float* __restrict__ C2,
    int M, int N, int K)
{
    __shared__ unsigned As[64 * GA_STR];
    __shared__ unsigned Bs[32 * GB_STR];

    int z = blockIdx.z;
    const float* B    = (z == 0) ? B0    : (z == 1) ? B1    : B2;
    const float* bias = (z == 0) ? bias0 : (z == 1) ? bias1 : bias2;
    float*       C    = (z == 0) ? C0    : (z == 1) ? C1    : C2;

    int t    = threadIdx.x;
    int lane = t & 31;
    int w    = t >> 5;
    int wm   = w >> 2;         // 0..1  (rows wm*32 .. +31)
    int wn   = w & 3;          // 0..3
    int bm   = blockIdx.y * 64;
    int bn   = blockIdx.x * 128;
    int lq   = lane >> 2;      // 0..7
    int lr4  = lane & 3;       // 0..3

    float acc[2][4][4];
    #pragma unroll
    for (int mt = 0; mt < 2; mt++)
        #pragma unroll
        for (int nt = 0; nt < 4; nt++)
            #pragma unroll
            for (int i = 0; i < 4; i++) acc[mt][nt][i] = 0.f;

    for (int kb = 0; kb < K; kb += 32) {
        // load A tile 64x32 (2 float4 per thread)
        #pragma unroll
        for (int i = 0; i < 2; i++) {
            int idx = t + i * 256;
            int m = idx >> 3, kc = idx & 7;
            float4 a4 = *(const float4*)&A[(size_t)(bm + m) * K + kb + kc * 4];
            uint4 u = make_uint4(f2tf(a4.x), f2tf(a4.y), f2tf(a4.z), f2tf(a4.w));
            *(uint4*)&As[m * GA_STR + kc * 4] = u;
        }
        // load B tile 32x128 (4 float4 per thread)
        #pragma unroll
        for (int i = 0; i < 4; i++) {
            int idx = t + i * 256;
            int r = idx >> 5, c = idx & 31;
            float4 b4 = *(const float4*)&B[(size_t)(kb + r) * N + bn + c * 4];
            uint4 u = make_uint4(f2tf(b4.x), f2tf(b4.y), f2tf(b4.z), f2tf(b4.w));
            *(uint4*)&Bs[r * GB_STR + c * 4] = u;
        }
        __syncthreads();

        #pragma unroll
        for (int k8 = 0; k8 < 4; k8++) {
            int kc = k8 * 8 + lr4;
            unsigned a[2][4];
            #pragma unroll
            for (int mt = 0; mt < 2; mt++) {
                int mr = wm * 32 + mt * 16 + lq;
                a[mt][0] = As[mr * GA_STR + kc];
                a[mt][1] = As[(mr + 8) * GA_STR + kc];
                a[mt][2] = As[mr * GA_STR + kc + 4];
                a[mt][3] = As[(mr + 8) * GA_STR + kc + 4];
            }
            unsigned b[4][2];
            #pragma unroll
            for (int nt = 0; nt < 4; nt++) {
                int nc = wn * 32 + nt * 8 + lq;
                b[nt][0] = Bs[kc * GB_STR + nc];
                b[nt][1] = Bs[(kc + 4) * GB_STR + nc];
            }
            #pragma unroll
            for (int mt = 0; mt < 2; mt++)
                #pragma unroll
                for (int nt = 0; nt < 4; nt++)
                    mma_tf32(acc[mt][nt], a[mt], b[nt][0], b[nt][1]);
        }
        __syncthreads();
    }

    // epilogue
    #pragma unroll
    for (int nt = 0; nt < 4; nt++) {
        int col = bn + wn * 32 + nt * 8 + 2 * lr4;
        float2 bi = *(const float2*)&bias[col];
        #pragma unroll
        for (int mt = 0; mt < 2; mt++) {
            int r0 = bm + wm * 32 + mt * 16 + lq;
            float2 o0 = make_float2(acc[mt][nt][0] + bi.x, acc[mt][nt][1] + bi.y);
            float2 o1 = make_float2(acc[mt][nt][2] + bi.x, acc[mt][nt][3] + bi.y);
            *(float2*)&C[(size_t)r0 * N + col] = o0;
            *(float2*)&C[(size_t)(r0 + 8) * N + col] = o1;
        }
    }
}

// ---------------------------------------------------------------------------
// TF32 tensor-core causal flash attention, 128q x 64k tiles (R13-proven).
// 256 threads = 8 warps; warp w owns rows w*16..w*16+15 and ALL 64 keys.
// KEY PERMUTATION: K B-fragments use kappa(j) = (j&1) ? j/2+4 : j/2 so the
// S-MMA output registers are directly the PV A-fragments (P never in smem).
// Smem (floats): Qs[128][68], Ks[64][72] (d-major), Vs[64][72].
// ---------------------------------------------------------------------------
#define FQ_STR 68
#define FK_STR 72
#define FA_SMEM ((128 * FQ_STR + 64 * FK_STR * 2) * 4)

__global__ __launch_bounds__(256, 2) void flash_attn_tc(
    const float* __restrict__ Q, const float* __restrict__ K,
    const float* __restrict__ V, float* __restrict__ O)
{
    extern __shared__ unsigned usm[];
    unsigned* Qs  = usm;                         // 128*68  (tf32, pre-scaled)
    unsigned* Ks  = Qs + 128 * FQ_STR;           // 64*72   [d][key]
    unsigned* Vsm = Ks + 64 * FK_STR;            // 64*72   [key][d]

    int bh = blockIdx.x;                  // 0..63
    int qt = 15 - blockIdx.y;             // long blocks first
    int b  = bh >> 4;
    int h  = bh & 15;
    int qb = qt * 128;

    const float* Qbase = Q + (size_t)b * SEQ * D_MODEL + h * D_K;
    const float* Kbase = K + (size_t)b * SEQ * D_MODEL + h * D_K;
    const float* Vbase = V + (size_t)b * SEQ * D_MODEL + h * D_K;
    float*       Obase = O + (size_t)b * SEQ * D_MODEL + h * D_K;

    int t    = threadIdx.x;
    int lane = t & 31;
    int w    = t >> 5;         // warp 0..7 -> rows w*16..+15
    int lq   = lane >> 2;      // 0..7
    int lr4  = lane & 3;       // 0..3
    int rw   = w * 16 + lq;    // warp-local row (first half)
    // permuted B-fragment key index within each 8-key group
    int pl   = (lq & 1) ? (lq >> 1) + 4 : (lq >> 1);

    // ---- load Q tile (128x64) as tf32, scale folded ----
    {
        int lr  = t >> 4;          // 0..15
        int ld4 = (t & 15) * 4;
        #pragma unroll
        for (int c = 0; c < 8; c++) {
            int r = lr + c * 16;
            float4 q4 = *(const float4*)&Qbase[(size_t)(qb + r) * D_MODEL + ld4];
            uint4 u = make_uint4(f2tf(q4.x * 0.125f), f2tf(q4.y * 0.125f),
                                 f2tf(q4.z * 0.125f), f2tf(q4.w * 0.125f));
            *(uint4*)&Qs[r * FQ_STR + ld4] = u;
        }
    }

    float o[8][4];
    #pragma unroll
    for (int nt = 0; nt < 8; nt++)
        #pragma unroll
        for (int i = 0; i < 4; i++) o[nt][i] = 0.f;

    float m0 = -FLT_MAX, m1 = -FLT_MAX, l0 = 0.f, l1 = 0.f;

    int kr = t & 63;           // K loader: row 0..63
    int kg = t >> 6;           // d-group 0..3
    int lr = t >> 4;           // V loader row base
    int ld4 = (t & 15) * 4;

    int nkt = 2 * qt + 2;
    for (int kt = 0; kt < nkt; kt++) {
        int kb = kt * 64;
        __syncthreads();   // all warps done reading Ks/Vs (and Q STS at kt=0)

        // K transposed: Ks[d][key]
        #pragma unroll
        for (int i = 0; i < 4; i++) {
            int d = kg * 16 + i * 4;
            float4 k4 = *(const float4*)&Kbase[(size_t)(kb + kr) * D_MODEL + d];
            Ks[(d + 0) * FK_STR + kr] = f2tf(k4.x);
            Ks[(d + 1) * FK_STR + kr] = f2tf(k4.y);
            Ks[(d + 2) * FK_STR + kr] = f2tf(k4.z);
            Ks[(d + 3) * FK_STR + kr] = f2tf(k4.w);
        }
        // V natural: Vs[key][d]
        #pragma unroll
        for (int c = 0; c < 4; c++) {
            int r = lr + c * 16;
            float4 v4 = *(const float4*)&Vbase[(size_t)(kb + r) * D_MODEL + ld4];
            uint4 u = make_uint4(f2tf(v4.x), f2tf(v4.y), f2tf(v4.z), f2tf(v4.w));
            *(uint4*)&Vsm[r * FK_STR + ld4] = u;
        }
        __syncthreads();

        // ---- S = Q @ K^T with permuted B keys ----
        float s[8][4];
        #pragma unroll
        for (int nt = 0; nt < 8; nt++)
            #pragma unroll
            for (int i = 0; i < 4; i++) s[nt][i] = 0.f;

        #pragma unroll
        for (int k8 = 0; k8 < 8; k8++) {
            int kc = k8 * 8 + lr4;
            unsigned a[4];
            a[0] = Qs[rw * FQ_STR + kc];
            a[1] = Qs[(rw + 8) * FQ_STR + kc];
            a[2] = Qs[rw * FQ_STR + kc + 4];
            a[3] = Qs[(rw + 8) * FQ_STR + kc + 4];
            #pragma unroll
            for (int nt = 0; nt < 8; nt++) {
                unsigned b0 = Ks[kc * FK_STR + nt * 8 + pl];
                unsigned b1 = Ks[(kc + 4) * FK_STR + nt * 8 + pl];
                mma_tf32(s[nt], a, b0, b1);
            }
        }

        // ---- causal mask on permuted keys (only last two key tiles clip) ----
        if (kt >= 2 * qt) {
            int row0 = qb + rw;
            #pragma unroll
            for (int nt = 0; nt < 8; nt++) {
                int key0 = kb + nt * 8 + lr4;
                int key1 = key0 + 4;
                if (key0 > row0)     s[nt][0] = -FLT_MAX;
                if (key1 > row0)     s[nt][1] = -FLT_MAX;
                if (key0 > row0 + 8) s[nt][2] = -FLT_MAX;
                if (key1 > row0 + 8) s[nt][3] = -FLT_MAX;
            }
        }

        // ---- online softmax, fully in registers (order-invariant) ----
        {
            float a0 = -FLT_MAX, a1 = -FLT_MAX;
            #pragma unroll
            for (int nt = 0; nt < 8; nt++) {
                a0 = fmaxf(a0, fmaxf(s[nt][0], s[nt][1]));
                a1 = fmaxf(a1, fmaxf(s[nt][2], s[nt][3]));
            }
            a0 = fmaxf(a0, __shfl_xor_sync(0xffffffffu, a0, 1));
            a0 = fmaxf(a0, __shfl_xor_sync(0xffffffffu, a0, 2));
            a1 = fmaxf(a1, __shfl_xor_sync(0xffffffffu, a1, 1));
            a1 = fmaxf(a1, __shfl_xor_sync(0xffffffffu, a1, 2));
            float mn0 = fmaxf(m0, a0), mn1 = fmaxf(m1, a1);
            float c0 = __expf(m0 - mn0), c1 = __expf(m1 - mn1);
            float sum0 = 0.f, sum1 = 0.f;
            #pragma unroll
            for (int nt = 0; nt < 8; nt++) {
                float p0 = __expf(s[nt][0] - mn0);
                float p1 = __expf(s[nt][1] - mn0);
                float p2 = __expf(s[nt][2] - mn1);
                float p3 = __expf(s[nt][3] - mn1);
                sum0 += p0 + p1;
                sum1 += p2 + p3;
                s[nt][0] = __uint_as_float(f2tf(p0));
                s[nt][1] = __uint_as_float(f2tf(p1));
                s[nt][2] = __uint_as_float(f2tf(p2));
                s[nt][3] = __uint_as_float(f2tf(p3));
            }
            sum0 += __shfl_xor_sync(0xffffffffu, sum0, 1);
            sum0 += __shfl_xor_sync(0xffffffffu, sum0, 2);
            sum1 += __shfl_xor_sync(0xffffffffu, sum1, 1);
            sum1 += __shfl_xor_sync(0xffffffffu, sum1, 2);
            l0 = l0 * c0 + sum0;
            l1 = l1 * c1 + sum1;
            m0 = mn0; m1 = mn1;
            #pragma unroll
            for (int nt = 0; nt < 8; nt++) {
                o[nt][0] *= c0; o[nt][1] *= c0;
                o[nt][2] *= c1; o[nt][3] *= c1;
            }
        }

        // ---- O += P @ V : A-fragment taken DIRECTLY from s registers ----
        #pragma unroll
        for (int k8 = 0; k8 < 8; k8++) {
            int kc = k8 * 8 + lr4;
            unsigned a[4];
            a[0] = __float_as_uint(s[k8][0]);   // row rw,   k = kc
            a[1] = __float_as_uint(s[k8][2]);   // row rw+8, k = kc
            a[2] = __float_as_uint(s[k8][1]);   // row rw,   k = kc+4
            a[3] = __float_as_uint(s[k8][3]);   // row rw+8, k = kc+4
            #pragma unroll
            for (int nt = 0; nt < 8; nt++) {
                unsigned b0 = Vsm[kc * FK_STR + nt * 8 + lq];
                unsigned b1 = Vsm[(kc + 4) * FK_STR + nt * 8 + lq];
                mma_tf32(o[nt], a, b0, b1);
            }
        }
    }

    // ---- normalize + write O (all state in registers) ----
    {
        float inv0 = 1.0f / l0;
        float inv1 = 1.0f / l1;
        int r0 = qb + rw;
        #pragma unroll
        for (int nt = 0; nt < 8; nt++) {
            int col = nt * 8 + 2 * lr4;
            *(float2*)&Obase[(size_t)r0 * D_MODEL + col] =
                make_float2(o[nt][0] * inv0, o[nt][1] * inv0);
            *(float2*)&Obase[(size_t)(r0 + 8) * D_MODEL + col] =
                make_float2(o[nt][2] * inv1, o[nt][3] * inv1);
        }
    }
}

// ---------------------------------------------------------------------------
// Host launcher
// ---------------------------------------------------------------------------
extern "C" void kernel_launch(void* const* d_in, const int* in_sizes, int n_in,
                              void* d_out, int out_size)
{
    const float* x  = (const float*)d_in[0];
    const float* wq = (const float*)d_in[1];
    const float* bq = (const float*)d_in[2];
    const float* wk = (const float*)d_in[3];
    const float* bk = (const float*)d_in[4];
    const float* wv = (const float*)d_in[5];
    const float* bv = (const float*)d_in[6];
    const float* wo = (const float*)d_in[7];
    const float* bo = (const float*)d_in[8];
    float* out = (float*)d_out;

    int M = in_sizes[0] / D_MODEL;   // B*S = 8192

    float *q, *k, *v, *attn;
    cudaGetSymbolAddress((void**)&q,    g_q);
    cudaGetSymbolAddress((void**)&k,    g_k);
    cudaGetSymbolAddress((void**)&v,    g_v);
    cudaGetSymbolAddress((void**)&attn, g_attn);

    cudaFuncSetAttribute(flash_attn_tc,
                         cudaFuncAttributeMaxDynamicSharedMemorySize, FA_SMEM);

    dim3 gblk(256);

    // Fused QKV projections (z selects weight/bias/output)
    dim3 ggrd3(D_MODEL / 128, M / 64, 3);
    gemm_tc<<<ggrd3, gblk>>>(x, wq, wk, wv, bq, bk, bv, q, k, v,
                             M, D_MODEL, D_MODEL);

    dim3 fgrd(BATCH * NUM_HEADS, SEQ / 128);
    flash_attn_tc<<<fgrd, 256, FA_SMEM>>>(q, k, v, attn);

    // Output projection (single operand set)
    dim3 ggrd1(D_MODEL / 128, M / 64, 1);
    gemm_tc<<<ggrd1, gblk>>>(attn, wo, wo, wo, bo, bo, bo, out, out, out,
                             M, D_MODEL, D_MODEL);
}